// round 4
// baseline (speedup 1.0000x reference)
#include <cuda_runtime.h>
#include <mma.h>
#include <cstdint>

using namespace nvcuda;

// Problem constants
#define NN 100000
#define EE 3200000
#define GGR 1024

// ---------------- scratch (device globals; no allocations allowed) ----------------
__device__ __align__(16) float g_agg [NN * 64];
__device__ __align__(16) float g_h1  [NN * 128];
__device__ __align__(16) float g_t   [NN * 128];
__device__ __align__(16) float g_z   [NN * 128];
__device__ __align__(16) float g_y   [NN * 64];
__device__ __align__(16) float g_stats[256];
__device__ __align__(16) float g_pool[GGR * 32];
__device__ __align__(16) float g_hd1 [GGR * 128];
__device__ __align__(16) float g_hd2 [GGR * 64];
__device__ __align__(16) int   g_deg [NN];
__device__ __align__(16) int   g_rs  [NN + 1];
__device__ __align__(16) int   g_cur [NN];
__device__ __align__(16) int   g_csr [EE];
__device__ __align__(16) int   g_part[128];

// ---------------- tiny utility kernels ----------------
__global__ void zero_i_kernel(int* p, int n){
    int i = blockIdx.x * blockDim.x + threadIdx.x;
    if (i < n) p[i] = 0;
}
__global__ void zero_f_kernel(float* p, int n){
    int i = blockIdx.x * blockDim.x + threadIdx.x;
    if (i < n) p[i] = 0.f;
}

// ---------------- CSR construction (by dst); edge_index is int32 ----------------
__global__ void hist_kernel(const int* __restrict__ ei, int* __restrict__ deg, int E){
    int e = blockIdx.x * blockDim.x + threadIdx.x;
    if (e < E){
        unsigned d = (unsigned)ei[E + e];
        if (d < (unsigned)NN) atomicAdd(&deg[d], 1);
    }
}

__global__ void scan_block_kernel(const int* __restrict__ deg, int* __restrict__ rs,
                                  int* __restrict__ part, int n){
    __shared__ int sm[1024];
    int t = threadIdx.x;
    int gi = blockIdx.x * 1024 + t;
    int v = (gi < n) ? deg[gi] : 0;
    sm[t] = v;
    __syncthreads();
    #pragma unroll
    for (int off = 1; off < 1024; off <<= 1){
        int xv = (t >= off) ? sm[t - off] : 0;
        __syncthreads();
        sm[t] += xv;
        __syncthreads();
    }
    if (gi < n) rs[gi] = sm[t] - v;           // exclusive
    if (t == 1023) part[blockIdx.x] = sm[1023];
}

__global__ void scan_part_kernel(int* part, int nb){
    __shared__ int sm[128];
    int t = threadIdx.x;
    sm[t] = (t < nb) ? part[t] : 0;
    __syncthreads();
    if (t == 0){
        int run = 0;
        for (int i = 0; i < nb; i++){ int v = sm[i]; sm[i] = run; run += v; }
    }
    __syncthreads();
    if (t < nb) part[t] = sm[t];
}

__global__ void scan_add_kernel(int* rs, const int* __restrict__ part, int* cur, int n, int E){
    int i = blockIdx.x * blockDim.x + threadIdx.x;
    if (i < n){
        int v = rs[i] + part[i >> 10];
        rs[i] = v;
        cur[i] = v;
    }
    if (i == 0) rs[n] = E;
}

__global__ void fill_kernel(const int* __restrict__ ei, int* __restrict__ cur,
                            int* __restrict__ csr, int E){
    int e = blockIdx.x * blockDim.x + threadIdx.x;
    if (e < E){
        unsigned d = (unsigned)ei[E + e];
        if (d < (unsigned)NN){
            int pos = atomicAdd(&cur[d], 1);
            if (pos >= 0 && pos < E) csr[pos] = ei[e];
        }
    }
}

// ---------------- CSR gather-aggregate: agg[i] = feat[i] + sum_{j in in(i)} feat[j] ----------------
template<int SH>
__global__ void gather_kernel(const float* __restrict__ feat, float* __restrict__ agg,
                              const int* __restrict__ rs, const int* __restrict__ csr, int n){
    const int W4 = 1 << SH;
    const int W  = W4 * 4;
    int tid = blockIdx.x * blockDim.x + threadIdx.x;
    int i = tid >> SH;
    if (i >= n) return;
    int q = (tid & (W4 - 1)) * 4;

    float4 acc = *(const float4*)(feat + (size_t)i * W + q);   // self term
    int a = rs[i], b = rs[i + 1];
    int j = a;
    for (; j + 4 <= b; j += 4){
        int s0 = csr[j], s1 = csr[j+1], s2 = csr[j+2], s3 = csr[j+3];
        float4 v0 = *(const float4*)(feat + (size_t)s0 * W + q);
        float4 v1 = *(const float4*)(feat + (size_t)s1 * W + q);
        float4 v2 = *(const float4*)(feat + (size_t)s2 * W + q);
        float4 v3 = *(const float4*)(feat + (size_t)s3 * W + q);
        acc.x += (v0.x + v1.x) + (v2.x + v3.x);
        acc.y += (v0.y + v1.y) + (v2.y + v3.y);
        acc.z += (v0.z + v1.z) + (v2.z + v3.z);
        acc.w += (v0.w + v1.w) + (v2.w + v3.w);
    }
    for (; j < b; ++j){
        int s = csr[j];
        float4 v = *(const float4*)(feat + (size_t)s * W + q);
        acc.x += v.x; acc.y += v.y; acc.z += v.z; acc.w += v.w;
    }
    *(float4*)(agg + (size_t)i * W + q) = acc;
}

// ---------------- error-compensated TF32 tensor-core GEMM (3-term Markidis split) ----------------
// out = [relu]( pre(A) @ W + bias ), pre(A) = A or relu(A + preb), optional BN-stats.
// A,W staged in smem as FP32; hi/lo tf32 split derived per-fragment in registers.
// acc = Ah@Wh + Ah@Wl + Al@Wh  (residual Al@Wl ~ 2^-22 -> effectively fp32 precision)
template<int FIN, int FOUT, bool PREB, bool RELU_OUT, bool STATS, bool OBIAS>
__global__ __launch_bounds__(256)
void tc_gemm(const float* __restrict__ A, const float* __restrict__ preb,
             const float* __restrict__ W, const float* __restrict__ bias,
             float* __restrict__ out, float* __restrict__ stats, int n)
{
    constexpr int LDA = FIN + 4;
    constexpr int LDW = FOUT + 4;
    constexpr int LDC = FOUT + 4;
    constexpr int SZ_A = 128 * LDA;
    constexpr int SZ_W = FIN * LDW;
    constexpr int SZ_C = 128 * LDC;
    constexpr int REG  = (SZ_A + SZ_W > SZ_C) ? (SZ_A + SZ_W) : SZ_C;
    constexpr int NF   = FOUT / 16;          // n fragments per warp

    extern __shared__ float smem[];
    float* sA = smem;                 // [128][LDA]   fp32 (phase 1)
    float* sW = smem + SZ_A;          // [FIN][LDW]   fp32 (phase 1)
    float* sC = smem;                 // [128][LDC]   (phase 2, overlays A/W)
    float* sS = smem + REG;           // [2*FOUT]     (stats)

    int tid  = threadIdx.x;
    int row0 = blockIdx.x * 128;

    if (STATS){
        for (int i = tid; i < 2 * FOUT; i += 256) sS[i] = 0.f;
    }

    // stage W (fp32)
    for (int i = tid; i < FIN * FOUT; i += 256){
        int k = i / FOUT, j = i - k * FOUT;
        sW[k * LDW + j] = W[i];
    }

    // stage A tile (fp32, guarded, zero-padded, optional pre-bias+relu)
    constexpr int K4 = FIN / 4;
    for (int idx = tid; idx < 128 * K4; idx += 256){
        int m = idx / K4, kq = idx - m * K4;
        int r = row0 + m;
        float4 v = make_float4(0.f, 0.f, 0.f, 0.f);
        if (r < n){
            v = *(const float4*)(A + (size_t)r * FIN + kq * 4);
            if (PREB){
                float4 pb = *(const float4*)(preb + kq * 4);
                v.x = fmaxf(v.x + pb.x, 0.f);
                v.y = fmaxf(v.y + pb.y, 0.f);
                v.z = fmaxf(v.z + pb.z, 0.f);
                v.w = fmaxf(v.w + pb.w, 0.f);
            }
        }
        *(float4*)(sA + m * LDA + kq * 4) = v;
    }
    __syncthreads();

    int w  = tid >> 5;
    int m0 = w * 16;

    wmma::fragment<wmma::accumulator, 16, 16, 8, float> acc[NF];
    #pragma unroll
    for (int f = 0; f < NF; f++) wmma::fill_fragment(acc[f], 0.f);

    #pragma unroll
    for (int k = 0; k < FIN; k += 8){
        wmma::fragment<wmma::matrix_a, 16, 16, 8, wmma::precision::tf32, wmma::row_major> ah, al;
        wmma::load_matrix_sync(ah, sA + m0 * LDA + k, LDA);
        #pragma unroll
        for (int e = 0; e < ah.num_elements; e++){
            float v = ah.x[e];
            float h = wmma::__float_to_tf32(v);
            ah.x[e] = h;
            al.x[e] = wmma::__float_to_tf32(v - h);
        }
        #pragma unroll
        for (int f = 0; f < NF; f++){
            wmma::fragment<wmma::matrix_b, 16, 16, 8, wmma::precision::tf32, wmma::row_major> bh, bl;
            wmma::load_matrix_sync(bh, sW + k * LDW + f * 16, LDW);
            #pragma unroll
            for (int e = 0; e < bh.num_elements; e++){
                float v = bh.x[e];
                float h = wmma::__float_to_tf32(v);
                bh.x[e] = h;
                bl.x[e] = wmma::__float_to_tf32(v - h);
            }
            wmma::mma_sync(acc[f], ah, bl, acc[f]);   // hi * lo
            wmma::mma_sync(acc[f], al, bh, acc[f]);   // lo * hi
            wmma::mma_sync(acc[f], ah, bh, acc[f]);   // hi * hi
        }
    }

    __syncthreads();   // all mma reads of sA/sW done before sC overlays them
    #pragma unroll
    for (int f = 0; f < NF; f++)
        wmma::store_matrix_sync(sC + m0 * LDC + f * 16, acc[f], LDC, wmma::mem_row_major);
    __syncthreads();

    // epilogue: bias, relu, store, BN-stats
    constexpr int CG = FOUT / 4;      // float4 column groups
    constexpr int RP = 256 / CG;      // row partitions
    int c4  = tid % CG;
    int rpt = tid / CG;

    float4 bv = make_float4(0.f, 0.f, 0.f, 0.f);
    if (OBIAS) bv = *(const float4*)(bias + c4 * 4);

    float s0 = 0.f, s1 = 0.f, s2 = 0.f, s3 = 0.f;
    float q0 = 0.f, q1 = 0.f, q2 = 0.f, q3 = 0.f;

    for (int r = rpt; r < 128; r += RP){
        int gr = row0 + r;
        if (gr >= n) continue;
        float4 v = *(float4*)(sC + r * LDC + c4 * 4);
        v.x += bv.x; v.y += bv.y; v.z += bv.z; v.w += bv.w;
        if (RELU_OUT){
            v.x = fmaxf(v.x, 0.f); v.y = fmaxf(v.y, 0.f);
            v.z = fmaxf(v.z, 0.f); v.w = fmaxf(v.w, 0.f);
        }
        *(float4*)(out + (size_t)gr * FOUT + c4 * 4) = v;
        if (STATS){
            s0 += v.x; s1 += v.y; s2 += v.z; s3 += v.w;
            q0 += v.x*v.x; q1 += v.y*v.y; q2 += v.z*v.z; q3 += v.w*v.w;
        }
    }

    if (STATS){
        atomicAdd(&sS[c4*4+0], s0); atomicAdd(&sS[c4*4+1], s1);
        atomicAdd(&sS[c4*4+2], s2); atomicAdd(&sS[c4*4+3], s3);
        atomicAdd(&sS[FOUT + c4*4+0], q0); atomicAdd(&sS[FOUT + c4*4+1], q1);
        atomicAdd(&sS[FOUT + c4*4+2], q2); atomicAdd(&sS[FOUT + c4*4+3], q3);
        __syncthreads();
        for (int i = tid; i < 2 * FOUT; i += 256)
            atomicAdd(&stats[i], sS[i]);
    }
}

// ---------------- BatchNorm apply ----------------
template<int F>
__global__ void bn_kernel(const float* __restrict__ t, const float* __restrict__ stats,
                          const float* __restrict__ gamma, const float* __restrict__ beta,
                          float* __restrict__ z, int n)
{
    int tid = blockIdx.x * blockDim.x + threadIdx.x;
    int total = n * (F / 4);
    if (tid >= total) return;
    int q = tid % (F / 4);
    int j = q * 4;
    float inv_n = 1.0f / n;
    float4 tv = ((const float4*)t)[tid];
    float4 r;
    {
        float mu = stats[j+0]*inv_n; float var = stats[F+j+0]*inv_n - mu*mu;
        float sc = gamma[j+0] * rsqrtf(var + 1e-5f); r.x = (tv.x - mu)*sc + beta[j+0];
    }
    {
        float mu = stats[j+1]*inv_n; float var = stats[F+j+1]*inv_n - mu*mu;
        float sc = gamma[j+1] * rsqrtf(var + 1e-5f); r.y = (tv.y - mu)*sc + beta[j+1];
    }
    {
        float mu = stats[j+2]*inv_n; float var = stats[F+j+2]*inv_n - mu*mu;
        float sc = gamma[j+2] * rsqrtf(var + 1e-5f); r.z = (tv.z - mu)*sc + beta[j+2];
    }
    {
        float mu = stats[j+3]*inv_n; float var = stats[F+j+3]*inv_n - mu*mu;
        float sc = gamma[j+3] * rsqrtf(var + 1e-5f); r.w = (tv.w - mu)*sc + beta[j+3];
    }
    ((float4*)z)[tid] = r;
}

// ---------------- BN(layer3) fused with global_add_pool ----------------
__global__ void bn_pool_kernel(const float* __restrict__ t, const float* __restrict__ stats,
                               const float* __restrict__ gamma, const float* __restrict__ beta,
                               const int* __restrict__ batch, float* __restrict__ pool, int n)
{
    int tid = blockIdx.x * blockDim.x + threadIdx.x;
    int total = n * 8;                 // 32 features / 4
    if (tid >= total) return;
    int i = tid >> 3;
    int q = tid & 7;
    int j = q * 4;
    float inv_n = 1.0f / n;
    float4 tv = ((const float4*)t)[tid];
    float vals[4] = {tv.x, tv.y, tv.z, tv.w};
    int g = batch[i];
    float* pp = pool + g * 32 + j;
    #pragma unroll
    for (int c = 0; c < 4; c++){
        float mu  = stats[j + c] * inv_n;
        float var = stats[32 + j + c] * inv_n - mu * mu;
        float sc  = gamma[j + c] * rsqrtf(var + 1e-5f);
        float zv  = (vals[c] - mu) * sc + beta[j + c];
        atomicAdd(pp + c, zv);
    }
}

// ---------------- final linear (64 -> 10) ----------------
__global__ void head3_kernel(const float* __restrict__ h2, const float* __restrict__ W,
                             const float* __restrict__ b, float* __restrict__ out)
{
    int tid = blockIdx.x * blockDim.x + threadIdx.x;
    if (tid >= GGR * 10) return;
    int r = tid / 10, c = tid - r * 10;
    float s = b[c];
    const float* hr = h2 + r * 64;
    #pragma unroll 16
    for (int k = 0; k < 64; k++)
        s = fmaf(hr[k], __ldg(&W[k * 10 + c]), s);
    out[tid] = s;
}

// ---------------- host ----------------
static inline int tc_smem_bytes(int FIN, int FOUT, bool STATS){
    int sz_a = 128 * (FIN + 4);
    int sz_w = FIN * (FOUT + 4);
    int sz_c = 128 * (FOUT + 4);
    int reg  = (sz_a + sz_w > sz_c) ? (sz_a + sz_w) : sz_c;
    return (reg + (STATS ? 2 * FOUT : 0)) * 4;
}

extern "C" void kernel_launch(void* const* d_in, const int* in_sizes, int n_in,
                              void* d_out, int out_size)
{
    const float* x     = (const float*)d_in[0];
    const int*   ei    = (const int*)d_in[1];     // int32
    const int*   batch = (const int*)d_in[2];     // int32
    const float* W1a = (const float*)d_in[3],  *b1a = (const float*)d_in[4];
    const float* W1b = (const float*)d_in[5],  *b1b = (const float*)d_in[6];
    const float* ga1 = (const float*)d_in[7],  *be1 = (const float*)d_in[8];
    const float* W2a = (const float*)d_in[9],  *b2a = (const float*)d_in[10];
    const float* W2b = (const float*)d_in[11], *b2b = (const float*)d_in[12];
    const float* ga2 = (const float*)d_in[13], *be2 = (const float*)d_in[14];
    const float* W3a = (const float*)d_in[15], *b3a = (const float*)d_in[16];
    const float* W3b = (const float*)d_in[17], *b3b = (const float*)d_in[18];
    const float* ga3 = (const float*)d_in[19], *be3 = (const float*)d_in[20];
    const float* Wf1 = (const float*)d_in[21], *bf1 = (const float*)d_in[22];
    const float* Wf2 = (const float*)d_in[23], *bf2 = (const float*)d_in[24];
    const float* Wf3 = (const float*)d_in[25], *bf3 = (const float*)d_in[26];
    float* out = (float*)d_out;

    const int N = NN, E = EE, G = GGR;

    float *agg, *h1, *t, *z, *y, *stats, *pool, *hd1, *hd2;
    int *deg, *rs, *cur, *csr, *part;
    cudaGetSymbolAddress((void**)&agg,  g_agg);
    cudaGetSymbolAddress((void**)&h1,   g_h1);
    cudaGetSymbolAddress((void**)&t,    g_t);
    cudaGetSymbolAddress((void**)&z,    g_z);
    cudaGetSymbolAddress((void**)&y,    g_y);
    cudaGetSymbolAddress((void**)&stats,g_stats);
    cudaGetSymbolAddress((void**)&pool, g_pool);
    cudaGetSymbolAddress((void**)&hd1,  g_hd1);
    cudaGetSymbolAddress((void**)&hd2,  g_hd2);
    cudaGetSymbolAddress((void**)&deg,  g_deg);
    cudaGetSymbolAddress((void**)&rs,   g_rs);
    cudaGetSymbolAddress((void**)&cur,  g_cur);
    cudaGetSymbolAddress((void**)&csr,  g_csr);
    cudaGetSymbolAddress((void**)&part, g_part);

    // opt-in smem limits
    cudaFuncSetAttribute((const void*)tc_gemm<64,128,false,true,false,true>,
                         cudaFuncAttributeMaxDynamicSharedMemorySize, tc_smem_bytes(64,128,false));
    cudaFuncSetAttribute((const void*)tc_gemm<128,128,false,true,true,true>,
                         cudaFuncAttributeMaxDynamicSharedMemorySize, tc_smem_bytes(128,128,true));
    cudaFuncSetAttribute((const void*)tc_gemm<128,64,false,false,false,false>,
                         cudaFuncAttributeMaxDynamicSharedMemorySize, tc_smem_bytes(128,64,false));
    cudaFuncSetAttribute((const void*)tc_gemm<64,64,true,true,true,true>,
                         cudaFuncAttributeMaxDynamicSharedMemorySize, tc_smem_bytes(64,64,true));
    cudaFuncSetAttribute((const void*)tc_gemm<64,32,false,false,false,false>,
                         cudaFuncAttributeMaxDynamicSharedMemorySize, tc_smem_bytes(64,32,false));
    cudaFuncSetAttribute((const void*)tc_gemm<32,32,true,true,true,true>,
                         cudaFuncAttributeMaxDynamicSharedMemorySize, tc_smem_bytes(32,32,true));
    cudaFuncSetAttribute((const void*)tc_gemm<32,128,false,true,false,true>,
                         cudaFuncAttributeMaxDynamicSharedMemorySize, tc_smem_bytes(32,128,false));
    cudaFuncSetAttribute((const void*)tc_gemm<128,64,false,true,false,true>,
                         cudaFuncAttributeMaxDynamicSharedMemorySize, tc_smem_bytes(128,64,false));

    const int TB = 256;
    const int gb = (N + 127) / 128;

    // -------- CSR build (reused for all 3 aggregations) --------
    zero_i_kernel<<<(N + TB - 1)/TB, TB>>>(deg, N);
    hist_kernel<<<(E + TB - 1)/TB, TB>>>(ei, deg, E);
    scan_block_kernel<<<(N + 1023)/1024, 1024>>>(deg, rs, part, N);
    scan_part_kernel<<<1, 128>>>(part, (N + 1023)/1024);
    scan_add_kernel<<<(N + TB - 1)/TB, TB>>>(rs, part, cur, N, E);
    fill_kernel<<<(E + TB - 1)/TB, TB>>>(ei, cur, csr, E);

    // -------- layer 1 --------
    gather_kernel<4><<<(N*16 + TB - 1)/TB, TB>>>(x, agg, rs, csr, N);
    tc_gemm<64,128,false,true,false,true>
        <<<gb, TB, tc_smem_bytes(64,128,false)>>>(agg, nullptr, W1a, b1a, h1, nullptr, N);
    zero_f_kernel<<<1, 256>>>(stats, 256);
    tc_gemm<128,128,false,true,true,true>
        <<<gb, TB, tc_smem_bytes(128,128,true)>>>(h1, nullptr, W1b, b1b, t, stats, N);
    bn_kernel<128><<<(N*32 + TB - 1)/TB, TB>>>(t, stats, ga1, be1, z, N);

    // -------- layer 2 (W2a folded before aggregation: 128 -> 64) --------
    tc_gemm<128,64,false,false,false,false>
        <<<gb, TB, tc_smem_bytes(128,64,false)>>>(z, nullptr, W2a, nullptr, y, nullptr, N);
    gather_kernel<4><<<(N*16 + TB - 1)/TB, TB>>>(y, agg, rs, csr, N);
    zero_f_kernel<<<1, 256>>>(stats, 256);
    tc_gemm<64,64,true,true,true,true>
        <<<gb, TB, tc_smem_bytes(64,64,true)>>>(agg, b2a, W2b, b2b, t, stats, N);
    bn_kernel<64><<<(N*16 + TB - 1)/TB, TB>>>(t, stats, ga2, be2, z, N);

    // -------- layer 3 (W3a folded: 64 -> 32) --------
    tc_gemm<64,32,false,false,false,false>
        <<<gb, TB, tc_smem_bytes(64,32,false)>>>(z, nullptr, W3a, nullptr, y, nullptr, N);
    gather_kernel<3><<<(N*8 + TB - 1)/TB, TB>>>(y, agg, rs, csr, N);
    zero_f_kernel<<<1, 256>>>(stats, 256);
    tc_gemm<32,32,true,true,true,true>
        <<<gb, TB, tc_smem_bytes(32,32,true)>>>(agg, b3a, W3b, b3b, t, stats, N);

    // -------- BN3 + global_add_pool fused --------
    zero_f_kernel<<<(G*32 + TB - 1)/TB, TB>>>(pool, G*32);
    bn_pool_kernel<<<(N*8 + TB - 1)/TB, TB>>>(t, stats, ga3, be3, batch, pool, N);

    // -------- classifier head --------
    tc_gemm<32,128,false,true,false,true>
        <<<(G + 127)/128, TB, tc_smem_bytes(32,128,false)>>>(pool, nullptr, Wf1, bf1, hd1, nullptr, G);
    tc_gemm<128,64,false,true,false,true>
        <<<(G + 127)/128, TB, tc_smem_bytes(128,64,false)>>>(hd1, nullptr, Wf2, bf2, hd2, nullptr, G);
    head3_kernel<<<(G*10 + TB - 1)/TB, TB>>>(hd2, Wf3, bf3, out);
}

// round 5
// speedup vs baseline: 1.2165x; 1.2165x over previous
#include <cuda_runtime.h>
#include <cstdint>

// Problem constants
#define NN 100000
#define EE 3200000
#define GGR 1024

// ---------------- scratch (device globals; no allocations allowed) ----------------
__device__ __align__(16) float g_h1  [NN * 128];
__device__ __align__(16) float g_t   [NN * 128];
__device__ __align__(16) float g_y   [NN * 64];
__device__ __align__(16) float g_stats[256];
__device__ __align__(16) float g_af  [256];
__device__ __align__(16) float g_pool[GGR * 32];
__device__ __align__(16) float g_hd1 [GGR * 128];
__device__ __align__(16) float g_hd2 [GGR * 64];
__device__ __align__(16) int   g_deg [NN];
__device__ __align__(16) int   g_rs  [NN + 1];
__device__ __align__(16) int   g_cur [NN];
__device__ __align__(16) int   g_csr [EE];
__device__ __align__(16) int   g_part[128];

// ---------------- tiny utility kernels ----------------
__global__ void zero_i_kernel(int* p, int n){
    int i = blockIdx.x * blockDim.x + threadIdx.x;
    if (i < n) p[i] = 0;
}
__global__ void zero_f_kernel(float* p, int n){
    int i = blockIdx.x * blockDim.x + threadIdx.x;
    if (i < n) p[i] = 0.f;
}

// ---------------- CSR construction (by dst); edge_index is int32 ----------------
__global__ void hist_kernel(const int* __restrict__ ei, int* __restrict__ deg, int E){
    int e = blockIdx.x * blockDim.x + threadIdx.x;
    if (e < E){
        unsigned d = (unsigned)ei[E + e];
        if (d < (unsigned)NN) atomicAdd(&deg[d], 1);
    }
}

__global__ void scan_block_kernel(const int* __restrict__ deg, int* __restrict__ rs,
                                  int* __restrict__ part, int n){
    __shared__ int sm[1024];
    int t = threadIdx.x;
    int gi = blockIdx.x * 1024 + t;
    int v = (gi < n) ? deg[gi] : 0;
    sm[t] = v;
    __syncthreads();
    #pragma unroll
    for (int off = 1; off < 1024; off <<= 1){
        int xv = (t >= off) ? sm[t - off] : 0;
        __syncthreads();
        sm[t] += xv;
        __syncthreads();
    }
    if (gi < n) rs[gi] = sm[t] - v;           // exclusive
    if (t == 1023) part[blockIdx.x] = sm[1023];
}

__global__ void scan_part_kernel(int* part, int nb){
    __shared__ int sm[128];
    int t = threadIdx.x;
    sm[t] = (t < nb) ? part[t] : 0;
    __syncthreads();
    if (t == 0){
        int run = 0;
        for (int i = 0; i < nb; i++){ int v = sm[i]; sm[i] = run; run += v; }
    }
    __syncthreads();
    if (t < nb) part[t] = sm[t];
}

__global__ void scan_add_kernel(int* rs, const int* __restrict__ part, int* cur, int n, int E){
    int i = blockIdx.x * blockDim.x + threadIdx.x;
    if (i < n){
        int v = rs[i] + part[i >> 10];
        rs[i] = v;
        cur[i] = v;
    }
    if (i == 0) rs[n] = E;
}

__global__ void fill_kernel(const int* __restrict__ ei, int* __restrict__ cur,
                            int* __restrict__ csr, int E){
    int e = blockIdx.x * blockDim.x + threadIdx.x;
    if (e < E){
        unsigned d = (unsigned)ei[E + e];
        if (d < (unsigned)NN){
            int pos = atomicAdd(&cur[d], 1);
            if (pos >= 0 && pos < E) csr[pos] = ei[e];
        }
    }
}

// ---------------- fused SIMT GEMM ----------------
// out = [relu]( pre(stage(A)) @ W + bias ),  optional BN-stats accumulation.
// Staging modes:
//   STG==0 (plain):  v = A[r]
//   STG==1 (gather): v = A[r] + sum_{j in in(r)} A[csr[j]]     (CSR aggregate)
//   STG==2 (affine): v = A[r]*af[j] + af[FIN+j]                (fused BatchNorm)
// PREB: v = relu(v + preb[j]) after staging (GIN inner activation).
// 64-row tile, 256 threads, per-thread 4 x RN register tile.
template<int FIN, int FOUT, int STG, bool PREB, bool RELU_OUT, bool STATS, bool OBIAS>
__global__ __launch_bounds__(256)
void gemm_kernel(const float* __restrict__ A, const float* __restrict__ preb,
                 const float* __restrict__ W, const float* __restrict__ bias,
                 float* __restrict__ out, float* __restrict__ stats,
                 const float* __restrict__ af,
                 const int* __restrict__ rs, const int* __restrict__ csr, int n)
{
    constexpr int LDA = FIN + 4;      // pad -> conflict-free row reads
    constexpr int RN  = FOUT / 16;    // 8, 4, 2
    constexpr int RM  = 4;
    extern __shared__ float sm[];
    float* sA = sm;                   // [64][LDA]
    float* sW = sm + 64 * LDA;        // [FIN][FOUT]
    float* sS = sW + FIN * FOUT;      // [2*FOUT] if STATS

    int tid  = threadIdx.x;
    int row0 = blockIdx.x * 64;

    if (STATS){
        for (int i = tid; i < 2 * FOUT; i += 256) sS[i] = 0.f;
    }
    for (int i = tid; i < FIN * FOUT / 4; i += 256)
        ((float4*)sW)[i] = ((const float4*)W)[i];

    constexpr int K4 = FIN / 4;
    for (int idx = tid; idx < 64 * K4; idx += 256){
        int m = idx / K4, kq = idx - m * K4;
        int r = row0 + m;
        float4 v = make_float4(0.f, 0.f, 0.f, 0.f);
        if (r < n){
            int q = kq * 4;
            v = *(const float4*)(A + (size_t)r * FIN + q);
            if constexpr (STG == 1){
                // CSR gather-aggregate fused into staging
                int a0 = rs[r], b0 = rs[r + 1];
                int j = a0;
                for (; j + 4 <= b0; j += 4){
                    int s0 = csr[j], s1 = csr[j+1], s2 = csr[j+2], s3 = csr[j+3];
                    float4 v0 = *(const float4*)(A + (size_t)s0 * FIN + q);
                    float4 v1 = *(const float4*)(A + (size_t)s1 * FIN + q);
                    float4 v2 = *(const float4*)(A + (size_t)s2 * FIN + q);
                    float4 v3 = *(const float4*)(A + (size_t)s3 * FIN + q);
                    v.x += (v0.x + v1.x) + (v2.x + v3.x);
                    v.y += (v0.y + v1.y) + (v2.y + v3.y);
                    v.z += (v0.z + v1.z) + (v2.z + v3.z);
                    v.w += (v0.w + v1.w) + (v2.w + v3.w);
                }
                for (; j < b0; ++j){
                    int s = csr[j];
                    float4 u = *(const float4*)(A + (size_t)s * FIN + q);
                    v.x += u.x; v.y += u.y; v.z += u.z; v.w += u.w;
                }
            } else if constexpr (STG == 2){
                // fused BatchNorm affine: v*scale + shift
                float4 sc = *(const float4*)(af + q);
                float4 sh = *(const float4*)(af + FIN + q);
                v.x = fmaf(v.x, sc.x, sh.x);
                v.y = fmaf(v.y, sc.y, sh.y);
                v.z = fmaf(v.z, sc.z, sh.z);
                v.w = fmaf(v.w, sc.w, sh.w);
            }
            if (PREB){
                float4 pb = *(const float4*)(preb + kq * 4);
                v.x = fmaxf(v.x + pb.x, 0.f);
                v.y = fmaxf(v.y + pb.y, 0.f);
                v.z = fmaxf(v.z + pb.z, 0.f);
                v.w = fmaxf(v.w + pb.w, 0.f);
            }
        }
        *(float4*)(sA + m * LDA + kq * 4) = v;
    }
    __syncthreads();

    int cg = tid & 15, rg = tid >> 4;
    int j0 = cg * RN, m0 = rg * RM;

    float acc[RM][RN];
    #pragma unroll
    for (int i = 0; i < RM; i++)
        #pragma unroll
        for (int jj = 0; jj < RN; jj++)
            acc[i][jj] = OBIAS ? bias[j0 + jj] : 0.f;

    #pragma unroll 4
    for (int k = 0; k < FIN; k++){
        float a[RM];
        #pragma unroll
        for (int i = 0; i < RM; i++) a[i] = sA[(m0 + i) * LDA + k];
        float w[RN];
        if constexpr (RN >= 4){
            #pragma unroll
            for (int jj = 0; jj < RN; jj += 4){
                float4 w4 = *(const float4*)(sW + k * FOUT + j0 + jj);
                w[jj] = w4.x; w[jj+1] = w4.y; w[jj+2] = w4.z; w[jj+3] = w4.w;
            }
        } else {
            float2 w2 = *(const float2*)(sW + k * FOUT + j0);
            w[0] = w2.x; w[1] = w2.y;
        }
        #pragma unroll
        for (int i = 0; i < RM; i++)
            #pragma unroll
            for (int jj = 0; jj < RN; jj++)
                acc[i][jj] = fmaf(a[i], w[jj], acc[i][jj]);
    }

    #pragma unroll
    for (int i = 0; i < RM; i++){
        int r = row0 + m0 + i;
        if (r < n){
            #pragma unroll
            for (int jj = 0; jj < RN; jj++)
                if (RELU_OUT) acc[i][jj] = fmaxf(acc[i][jj], 0.f);
            if constexpr (RN >= 4){
                #pragma unroll
                for (int jj = 0; jj < RN; jj += 4){
                    float4 v = make_float4(acc[i][jj], acc[i][jj+1], acc[i][jj+2], acc[i][jj+3]);
                    *(float4*)(out + (size_t)r * FOUT + j0 + jj) = v;
                }
            } else {
                float2 v = make_float2(acc[i][0], acc[i][1]);
                *(float2*)(out + (size_t)r * FOUT + j0) = v;
            }
        }
    }

    if (STATS){
        float s[RN], q[RN];
        #pragma unroll
        for (int jj = 0; jj < RN; jj++){ s[jj] = 0.f; q[jj] = 0.f; }
        #pragma unroll
        for (int i = 0; i < RM; i++){
            int r = row0 + m0 + i;
            if (r < n){
                #pragma unroll
                for (int jj = 0; jj < RN; jj++){
                    float v = acc[i][jj];
                    s[jj] += v; q[jj] += v * v;
                }
            }
        }
        #pragma unroll
        for (int jj = 0; jj < RN; jj++){
            atomicAdd(&sS[j0 + jj], s[jj]);
            atomicAdd(&sS[FOUT + j0 + jj], q[jj]);
        }
        __syncthreads();
        for (int i = tid; i < 2 * FOUT; i += 256)
            atomicAdd(&stats[i], sS[i]);
    }
}

// ---------------- stats -> affine (scale, shift) ----------------
__global__ void affine_kernel(const float* __restrict__ stats,
                              const float* __restrict__ gamma, const float* __restrict__ beta,
                              float* __restrict__ af, int F, float inv_n)
{
    int j = threadIdx.x;
    if (j < F){
        float mu  = stats[j] * inv_n;
        float var = stats[F + j] * inv_n - mu * mu;
        float sc  = gamma[j] * rsqrtf(var + 1e-5f);
        af[j]     = sc;
        af[F + j] = beta[j] - mu * sc;
    }
}

// ---------------- BN(layer3, via affine) fused with global_add_pool ----------------
__global__ void bn_pool_kernel(const float* __restrict__ t, const float* __restrict__ af,
                               const int* __restrict__ batch, float* __restrict__ pool, int n)
{
    int tid = blockIdx.x * blockDim.x + threadIdx.x;
    int total = n * 8;                 // 32 features / 4
    if (tid >= total) return;
    int i = tid >> 3;
    int q = tid & 7;
    int j = q * 4;
    float4 tv = ((const float4*)t)[tid];
    float4 sc = *(const float4*)(af + j);
    float4 sh = *(const float4*)(af + 32 + j);
    int g = batch[i];
    float* pp = pool + g * 32 + j;
    atomicAdd(pp + 0, fmaf(tv.x, sc.x, sh.x));
    atomicAdd(pp + 1, fmaf(tv.y, sc.y, sh.y));
    atomicAdd(pp + 2, fmaf(tv.z, sc.z, sh.z));
    atomicAdd(pp + 3, fmaf(tv.w, sc.w, sh.w));
}

// ---------------- final linear (64 -> 10) ----------------
__global__ void head3_kernel(const float* __restrict__ h2, const float* __restrict__ W,
                             const float* __restrict__ b, float* __restrict__ out)
{
    int tid = blockIdx.x * blockDim.x + threadIdx.x;
    if (tid >= GGR * 10) return;
    int r = tid / 10, c = tid - r * 10;
    float s = b[c];
    const float* hr = h2 + r * 64;
    #pragma unroll 16
    for (int k = 0; k < 64; k++)
        s = fmaf(hr[k], __ldg(&W[k * 10 + c]), s);
    out[tid] = s;
}

// ---------------- host ----------------
static inline int smem_bytes(int FIN, int FOUT, bool STATS){
    return (64 * (FIN + 4) + FIN * FOUT + (STATS ? 2 * FOUT : 0)) * 4;
}

extern "C" void kernel_launch(void* const* d_in, const int* in_sizes, int n_in,
                              void* d_out, int out_size)
{
    const float* x     = (const float*)d_in[0];
    const int*   ei    = (const int*)d_in[1];     // int32
    const int*   batch = (const int*)d_in[2];     // int32
    const float* W1a = (const float*)d_in[3],  *b1a = (const float*)d_in[4];
    const float* W1b = (const float*)d_in[5],  *b1b = (const float*)d_in[6];
    const float* ga1 = (const float*)d_in[7],  *be1 = (const float*)d_in[8];
    const float* W2a = (const float*)d_in[9],  *b2a = (const float*)d_in[10];
    const float* W2b = (const float*)d_in[11], *b2b = (const float*)d_in[12];
    const float* ga2 = (const float*)d_in[13], *be2 = (const float*)d_in[14];
    const float* W3a = (const float*)d_in[15], *b3a = (const float*)d_in[16];
    const float* W3b = (const float*)d_in[17], *b3b = (const float*)d_in[18];
    const float* ga3 = (const float*)d_in[19], *be3 = (const float*)d_in[20];
    const float* Wf1 = (const float*)d_in[21], *bf1 = (const float*)d_in[22];
    const float* Wf2 = (const float*)d_in[23], *bf2 = (const float*)d_in[24];
    const float* Wf3 = (const float*)d_in[25], *bf3 = (const float*)d_in[26];
    float* out = (float*)d_out;

    const int N = NN, E = EE, G = GGR;

    float *h1, *t, *y, *stats, *af, *pool, *hd1, *hd2;
    int *deg, *rs, *cur, *csr, *part;
    cudaGetSymbolAddress((void**)&h1,   g_h1);
    cudaGetSymbolAddress((void**)&t,    g_t);
    cudaGetSymbolAddress((void**)&y,    g_y);
    cudaGetSymbolAddress((void**)&stats,g_stats);
    cudaGetSymbolAddress((void**)&af,   g_af);
    cudaGetSymbolAddress((void**)&pool, g_pool);
    cudaGetSymbolAddress((void**)&hd1,  g_hd1);
    cudaGetSymbolAddress((void**)&hd2,  g_hd2);
    cudaGetSymbolAddress((void**)&deg,  g_deg);
    cudaGetSymbolAddress((void**)&rs,   g_rs);
    cudaGetSymbolAddress((void**)&cur,  g_cur);
    cudaGetSymbolAddress((void**)&csr,  g_csr);
    cudaGetSymbolAddress((void**)&part, g_part);

    // opt-in smem limits for >48KB instantiations
    cudaFuncSetAttribute((const void*)gemm_kernel<64,128,1,false,true,false,true>,
                         cudaFuncAttributeMaxDynamicSharedMemorySize, smem_bytes(64,128,false));
    cudaFuncSetAttribute((const void*)gemm_kernel<128,128,0,false,true,true,true>,
                         cudaFuncAttributeMaxDynamicSharedMemorySize, smem_bytes(128,128,true));
    cudaFuncSetAttribute((const void*)gemm_kernel<128,64,2,false,false,false,false>,
                         cudaFuncAttributeMaxDynamicSharedMemorySize, smem_bytes(128,64,false));
    cudaFuncSetAttribute((const void*)gemm_kernel<128,64,0,false,true,false,true>,
                         cudaFuncAttributeMaxDynamicSharedMemorySize, smem_bytes(128,64,false));

    const int TB = 256;
    const int gb = (N + 63) / 64;

    // -------- CSR build (reused by all 3 fused aggregations) --------
    zero_i_kernel<<<(N + TB - 1)/TB, TB>>>(deg, N);
    hist_kernel<<<(E + TB - 1)/TB, TB>>>(ei, deg, E);
    scan_block_kernel<<<(N + 1023)/1024, 1024>>>(deg, rs, part, N);
    scan_part_kernel<<<1, 128>>>(part, (N + 1023)/1024);
    scan_add_kernel<<<(N + TB - 1)/TB, TB>>>(rs, part, cur, N, E);
    fill_kernel<<<(E + TB - 1)/TB, TB>>>(ei, cur, csr, E);

    // -------- layer 1: h1 = relu( (x + agg(x)) @ W1a + b1a )  [gather fused] --------
    gemm_kernel<64,128,1,false,true,false,true>
        <<<gb, TB, smem_bytes(64,128,false)>>>(x, nullptr, W1a, b1a, h1, nullptr, nullptr, rs, csr, N);
    zero_f_kernel<<<1, 256>>>(stats, 256);
    gemm_kernel<128,128,0,false,true,true,true>
        <<<gb, TB, smem_bytes(128,128,true)>>>(h1, nullptr, W1b, b1b, t, stats, nullptr, nullptr, nullptr, N);
    affine_kernel<<<1, 128>>>(stats, ga1, be1, af, 128, 1.0f/N);

    // -------- layer 2: y = BN1(t) @ W2a  [BN fused]; then GIN  [gather fused] --------
    gemm_kernel<128,64,2,false,false,false,false>
        <<<gb, TB, smem_bytes(128,64,false)>>>(t, nullptr, W2a, nullptr, y, nullptr, af, nullptr, nullptr, N);
    zero_f_kernel<<<1, 256>>>(stats, 256);
    gemm_kernel<64,64,1,true,true,true,true>
        <<<gb, TB, smem_bytes(64,64,true)>>>(y, b2a, W2b, b2b, t, stats, nullptr, rs, csr, N);
    affine_kernel<<<1, 128>>>(stats, ga2, be2, af, 64, 1.0f/N);

    // -------- layer 3 --------
    gemm_kernel<64,32,2,false,false,false,false>
        <<<gb, TB, smem_bytes(64,32,false)>>>(t, nullptr, W3a, nullptr, y, nullptr, af, nullptr, nullptr, N);
    zero_f_kernel<<<1, 256>>>(stats, 256);
    gemm_kernel<32,32,1,true,true,true,true>
        <<<gb, TB, smem_bytes(32,32,true)>>>(y, b3a, W3b, b3b, t, stats, nullptr, rs, csr, N);
    affine_kernel<<<1, 128>>>(stats, ga3, be3, af, 32, 1.0f/N);

    // -------- BN3 + global_add_pool fused --------
    zero_f_kernel<<<(G*32 + TB - 1)/TB, TB>>>(pool, G*32);
    bn_pool_kernel<<<(N*8 + TB - 1)/TB, TB>>>(t, af, batch, pool, N);

    // -------- classifier head --------
    gemm_kernel<32,128,0,false,true,false,true>
        <<<(G + 63)/64, TB, smem_bytes(32,128,false)>>>(pool, nullptr, Wf1, bf1, hd1, nullptr, nullptr, nullptr, nullptr, G);
    gemm_kernel<128,64,0,false,true,false,true>
        <<<(G + 63)/64, TB, smem_bytes(128,64,false)>>>(hd1, nullptr, Wf2, bf2, hd2, nullptr, nullptr, nullptr, nullptr, G);
    head3_kernel<<<(G*10 + TB - 1)/TB, TB>>>(hd2, Wf3, bf3, out);
}